// round 8
// baseline (speedup 1.0000x reference)
#include <cuda_runtime.h>
#include <math.h>

namespace {
constexpr int NDIM   = 4;
constexpr int KW     = 32;      // N_WIDTH total
constexpr int KQ     = 8;       // widths per CTA (k split 4 ways)
constexpr int NN     = 193;     // N_NODES
constexpr int NELEM  = 64;
constexpr int TILE_I = 320;
constexpr int THREADS = 512;
constexpr int SPW    = TILE_I / 16;           // samples per warp = 20
constexpr int QPW    = SPW / 4;               // quads per warp = 5

constexpr int NC_IN_Q  = NELEM * 4 * KQ;      // 2048 float4 per k-quarter
constexpr int NC_OUT_Q = NELEM * KQ;          // 512  float4 per k-quarter
constexpr int NC_IN    = NC_IN_Q * 4;         // 8192
constexpr int NC       = NC_IN + NC_OUT_Q * 4;// 10240

// smem layout in float4 units
constexpr int OFF_CIN  = 0;                    // [(e*4+j)*8 + kk]
constexpr int OFF_COUT = OFF_CIN  + NC_IN_Q;   // [e*8 + kk]
constexpr int OFF_XR   = OFF_COUT + NC_OUT_Q;  // float4 [TILE_I]
constexpr int OFF_E4   = OFF_XR   + TILE_I;    // int4   [TILE_I]
constexpr int SMEM_V4  = OFF_E4   + TILE_I;    // 3200
constexpr int SMEM_BYTES = SMEM_V4 * 16;       // 51200 B -> 3 CTAs/SM
}

// coefficient tables grouped by k-quarter, rebuilt per call (deterministic)
__device__ float4 g_coef[NC];

__global__ void kann_prep(const float* __restrict__ Win,
                          const float* __restrict__ Wout)
{
    // basis -> monomial matrix, nodes {-1,-1/3,1/3,1}
    const float g00 = -0.0625f, g01 =  0.0625f, g02 =  0.5625f, g03 = -0.5625f;
    const float g10 =  0.5625f, g11 = -1.6875f, g12 = -0.5625f, g13 =  1.6875f;
    const float g20 =  0.5625f, g21 =  1.6875f, g22 = -0.5625f, g23 = -1.6875f;
    const float g30 = -0.0625f, g31 = -0.0625f, g32 =  0.5625f, g33 =  0.5625f;

    int t = blockIdx.x * blockDim.x + threadIdx.x;
    if (t < NC_IN) {
        int kq = t >> 11;            // which k-quarter
        int r  = t & 2047;
        int kk = r & 7;
        int ej = r >> 3;
        int j  = ej & 3;
        int e  = ej >> 2;
        int k  = kq * KQ + kk;
        const float* g = Win + k * (NN * NDIM) + (3 * e) * NDIM + j;
        float w0 = g[0], w1 = g[NDIM], w2 = g[2 * NDIM], w3 = g[3 * NDIM];
        float4 a;
        a.x = w0 * g00 + w1 * g10 + w2 * g20 + w3 * g30;
        a.y = w0 * g01 + w1 * g11 + w2 * g21 + w3 * g31;
        a.z = w0 * g02 + w1 * g12 + w2 * g22 + w3 * g32;
        a.w = w0 * g03 + w1 * g13 + w2 * g23 + w3 * g33;
        g_coef[t] = a;
    } else if (t < NC) {
        int u  = t - NC_IN;
        int kq = u >> 9;
        int r  = u & 511;
        int kk = r & 7;
        int e  = r >> 3;
        int k  = kq * KQ + kk;
        const float* g = Wout + k * NN + 3 * e;
        float w0 = g[0], w1 = g[1], w2 = g[2], w3 = g[3];
        float4 b;
        b.x = w0 * g00 + w1 * g10 + w2 * g20 + w3 * g30;
        b.y = w0 * g01 + w1 * g11 + w2 * g21 + w3 * g31;
        b.z = w0 * g02 + w1 * g12 + w2 * g22 + w3 * g32;
        b.w = w0 * g03 + w1 * g13 + w2 * g23 + w3 * g33;
        g_coef[t] = b;
    }
}

__global__ __launch_bounds__(THREADS, 3)
void kann_kernel(const float* __restrict__ x,
                 float* __restrict__ out,
                 int I)
{
    extern __shared__ float4 smv[];
    float4* sCin  = smv + OFF_CIN;
    float4* sCout = smv + OFF_COUT;
    float4* sXR   = smv + OFF_XR;
    int4*   sE4   = (int4*)(smv + OFF_E4);

    const int tid    = threadIdx.x;
    const int i_base = blockIdx.x * TILE_I;
    const int kq     = blockIdx.y;
    const int k0     = kq * KQ;

    // ---- stage this quarter's coeff tables (coalesced LDG.128 -> STS.128) ----
    #pragma unroll
    for (int it = 0; it < NC_IN_Q / THREADS; it++) {
        int idx = it * THREADS + tid;
        sCin[idx] = g_coef[kq * NC_IN_Q + idx];
    }
    if (tid < NC_OUT_Q)
        sCout[tid] = g_coef[NC_IN + kq * NC_OUT_Q + tid];

    // ---- phase 1: per-sample transform (xr, element) for all 4 dims ----
    if (tid < TILE_I) {
        const int i = i_base + tid;
        float4 xr4 = {0.f, 0.f, 0.f, 0.f};
        int4   e4  = {0, 0, 0, 0};
        if (i < I) {
            float4 xv = ((const float4*)x)[i];
            #pragma unroll
            for (int j = 0; j < 4; j++) {
                float v  = (j == 0) ? xv.x : (j == 1) ? xv.y : (j == 2) ? xv.z : xv.w;
                float xs = 192.0f * (v + 1.0f) / 2.0f;
                float fe = floorf(xs / 3.0f);
                fe = fminf(fmaxf(fe, 0.0f), 63.0f);
                float nl = 3.0f * fe;
                float xr = 2.0f * (xs - nl) / 3.0f - 1.0f;
                if (j == 0) { xr4.x = xr; e4.x = (int)fe; }
                if (j == 1) { xr4.y = xr; e4.y = (int)fe; }
                if (j == 2) { xr4.z = xr; e4.z = (int)fe; }
                if (j == 3) { xr4.w = xr; e4.w = (int)fe; }
            }
        }
        sXR[tid] = xr4;
        sE4[tid] = e4;
    }
    __syncthreads();

    // ---- phase 2: warp = 4 samples (8-lane groups), lane&7 = width kk ----
    const int warp = tid >> 5;
    const int lane = tid & 31;
    const int sq   = lane >> 3;                 // sample within quad
    const int kk   = lane & 7;
    const int IK   = I * KW;

    #pragma unroll
    for (int q = 0; q < QPW; q++) {
        const int li = warp * SPW + q * 4 + sq;
        const int i  = i_base + li;
        const float4 xr4 = sXR[li];
        const int4   e4  = sE4[li];

        float tv = 0.f, dtv = 0.f, ddtv = 0.f;
        #pragma unroll
        for (int j = 0; j < 4; j++) {
            float xr = (j == 0) ? xr4.x : (j == 1) ? xr4.y : (j == 2) ? xr4.z : xr4.w;
            int   e  = (j == 0) ? e4.x  : (j == 1) ? e4.y  : (j == 2) ? e4.z  : e4.w;
            float4 a = sCin[(((e << 2) | j) << 3) + kk];   // LDS.128, 8-lane contiguous
            // simultaneous Horner: p, p', p''/2 share intermediates
            float h1 = fmaf(a.w, xr, a.z);
            float h2 = fmaf(h1,  xr, a.y);
            float h3 = fmaf(h2,  xr, a.x);
            float q2 = fmaf(a.w, xr, h1);
            float q3 = fmaf(q2,  xr, h2);
            float r  = fmaf(a.w, xr, q2);
            tv   += h3;
            dtv  += q3;
            ddtv += r;
        }
        dtv  *= 64.0f;    // p'/delta,      delta = 1/64 exactly
        ddtv *= 8192.0f;  // 2*r/delta^2

        // outer layer on t, domain [-3,3]
        float xs = 192.0f * (tv + 3.0f) / 6.0f;
        float fe = floorf(xs / 3.0f);
        fe = fminf(fmaxf(fe, 0.0f), 63.0f);
        float nl = 3.0f * fe;
        float xr = 2.0f * (xs - nl) / 3.0f - 1.0f;

        float4 b = sCout[((int)fe << 3) + kk];             // LDS.128
        float y = fmaf(fmaf(fmaf(b.w, xr, b.z), xr, b.y), xr, b.x);

        if (i < I) {
            int o = i * KW + k0 + kk;
            out[o]          = y;
            out[o + IK]     = tv;
            out[o + 2 * IK] = dtv;
            out[o + 3 * IK] = ddtv;
        }
    }
}

extern "C" void kernel_launch(void* const* d_in, const int* in_sizes, int n_in,
                              void* d_out, int out_size)
{
    const float* x    = (const float*)d_in[0];
    const float* Win  = (const float*)d_in[1];
    const float* Wout = (const float*)d_in[2];
    float* out = (float*)d_out;

    int I = in_sizes[0] / NDIM;                      // 32768
    dim3 grid((I + TILE_I - 1) / TILE_I, 4);         // 103 x 4 = 412 CTAs (<=444 slots)

    kann_prep<<<(NC + 255) / 256, 256>>>(Win, Wout);

    cudaFuncSetAttribute(kann_kernel,
                         cudaFuncAttributeMaxDynamicSharedMemorySize, SMEM_BYTES);
    kann_kernel<<<grid, THREADS, SMEM_BYTES>>>(x, out, I);
}

// round 9
// speedup vs baseline: 1.1400x; 1.1400x over previous
#include <cuda_runtime.h>
#include <math.h>

namespace {
constexpr int NDIM   = 4;
constexpr int KW     = 32;      // N_WIDTH
constexpr int NN     = 193;     // N_NODES
constexpr int NELEM  = 64;
constexpr int TILE_I = 224;
constexpr int THREADS = 1024;
constexpr int IPW    = TILE_I / 32;            // samples per warp = 7

constexpr int NC_IN  = NELEM * 4 * KW;         // 8192 float4 coeff sets (inner)
constexpr int NC_OUT = NELEM * KW;             // 2048 float4 coeff sets (outer)
constexpr int NC     = NC_IN + NC_OUT;         // 10240

// smem layout in float4 units
constexpr int OFF_CIN  = 0;                    // [(e*4+j)*32 + k] -> a0..a3
constexpr int OFF_COUT = OFF_CIN  + NC_IN;     // [e*32 + k]      -> b0..b3
constexpr int OFF_XR   = OFF_COUT + NC_OUT;    // float4 [TILE_I]  xr per dim
constexpr int OFF_E4   = OFF_XR   + TILE_I;    // int4   [TILE_I]  elem per dim
constexpr int SMEM_V4  = OFF_E4   + TILE_I;    // 10688
constexpr int SMEM_BYTES = SMEM_V4 * 16;       // 171008 B (1 CTA/SM)

constexpr float THIRD = 0.33333334f;           // RN(1/3)
}

// coefficient tables, rebuilt by prep kernel each call (deterministic)
__device__ float4 g_coef[NC];

// exact floor(div_rn(xs,3)) for xs in [0,192] without FP division:
// no float sits in the div-by-3 round-up window across an integer, so
// floor(xs/3) == n with 3n <= xs < 3n+3; recover n by recip-mult + fixup.
__device__ __forceinline__ float floor_div3(float xs) {
    float fe = floorf(xs * THIRD);
    float r  = fmaf(-3.0f, fe, xs);            // exact: 3*fe exact, Sterbenz
    fe += (r >= 3.0f) ? 1.0f : 0.0f;
    fe -= (r < 0.0f)  ? 1.0f : 0.0f;
    return fe;
}

__global__ void kann_prep(const float* __restrict__ Win,
                          const float* __restrict__ Wout)
{
    // basis -> monomial matrix, nodes {-1,-1/3,1/3,1}
    const float g00 = -0.0625f, g01 =  0.0625f, g02 =  0.5625f, g03 = -0.5625f;
    const float g10 =  0.5625f, g11 = -1.6875f, g12 = -0.5625f, g13 =  1.6875f;
    const float g20 =  0.5625f, g21 =  1.6875f, g22 = -0.5625f, g23 = -1.6875f;
    const float g30 = -0.0625f, g31 = -0.0625f, g32 =  0.5625f, g33 =  0.5625f;

    int t = blockIdx.x * blockDim.x + threadIdx.x;
    if (t < NC_IN) {
        int k   = t & 31;
        int e4j = t >> 5;
        int j   = e4j & 3;
        int e   = e4j >> 2;
        const float* g = Win + k * (NN * NDIM) + (3 * e) * NDIM + j;
        float w0 = g[0], w1 = g[NDIM], w2 = g[2 * NDIM], w3 = g[3 * NDIM];
        float4 a;
        a.x = w0 * g00 + w1 * g10 + w2 * g20 + w3 * g30;
        a.y = w0 * g01 + w1 * g11 + w2 * g21 + w3 * g31;
        a.z = w0 * g02 + w1 * g12 + w2 * g22 + w3 * g32;
        a.w = w0 * g03 + w1 * g13 + w2 * g23 + w3 * g33;
        g_coef[t] = a;
    } else if (t < NC) {
        int u = t - NC_IN;
        int k = u & 31;
        int e = u >> 5;
        const float* g = Wout + k * NN + 3 * e;
        float w0 = g[0], w1 = g[1], w2 = g[2], w3 = g[3];
        float4 b;
        b.x = w0 * g00 + w1 * g10 + w2 * g20 + w3 * g30;
        b.y = w0 * g01 + w1 * g11 + w2 * g21 + w3 * g31;
        b.z = w0 * g02 + w1 * g12 + w2 * g22 + w3 * g32;
        b.w = w0 * g03 + w1 * g13 + w2 * g23 + w3 * g33;
        g_coef[t] = b;
    }
#if __CUDA_ARCH__ >= 900
    cudaTriggerProgrammaticLaunchCompletion();
#endif
}

__global__ __launch_bounds__(THREADS, 1)
void kann_kernel(const float* __restrict__ x,
                 float* __restrict__ out,
                 int I)
{
    extern __shared__ float4 smv[];
    float4* sCin  = smv + OFF_CIN;
    float4* sCout = smv + OFF_COUT;
    float4* sXR   = smv + OFF_XR;
    int4*   sE4   = (int4*)(smv + OFF_E4);
    float*  sXRf  = (float*)sXR;                 // scalar view [TILE_I*4]
    int*    sEf   = (int*)sE4;

    const int tid    = threadIdx.x;
    const int i_base = blockIdx.x * TILE_I;

    // ---- phase 1 first (depends only on x, overlaps prep via PDL) ----
    if (tid < TILE_I * NDIM) {
        const int li = tid >> 2;
        const int j  = tid & 3;
        const int i  = i_base + li;
        float xr = 0.f;
        int   ei = 0;
        if (i < I) {
            float v  = x[i * NDIM + j];
            float xs = 192.0f * (v + 1.0f) / 2.0f;          // exact /2
            float fe = floor_div3(xs);
            fe = fminf(fmaxf(fe, 0.0f), 63.0f);
            float nl = 3.0f * fe;                            // exact
            xr = fmaf(2.0f * (xs - nl), THIRD, -1.0f);
            ei = (int)fe;
        }
        sXRf[tid] = xr;
        sEf[tid]  = ei;
    }

#if __CUDA_ARCH__ >= 900
    cudaGridDependencySynchronize();             // wait for prep's g_coef
#endif

    // ---- stage coefficient tables: coalesced LDG.128 -> conflict-free STS.128
    #pragma unroll
    for (int it = 0; it < NC / THREADS; it++) {
        int idx = it * THREADS + tid;
        smv[idx] = g_coef[idx];
    }
    __syncthreads();

    // ---- phase 2: warp = one sample, lane = width k ----
    const int warp = tid >> 5;
    const int lane = tid & 31;
    const int IK   = I * KW;

    #pragma unroll
    for (int s = 0; s < IPW; s++) {
        const int li = warp * IPW + s;
        const int i  = i_base + li;
        const float4 xr4 = sXR[li];
        const int4   e4  = sE4[li];

        float tv = 0.f, dtv = 0.f, ddtv = 0.f;
        #pragma unroll
        for (int j = 0; j < 4; j++) {
            float xr = (j == 0) ? xr4.x : (j == 1) ? xr4.y : (j == 2) ? xr4.z : xr4.w;
            int   e  = (j == 0) ? e4.x  : (j == 1) ? e4.y  : (j == 2) ? e4.z  : e4.w;
            float4 a = sCin[((e << 2) | j) * KW + lane];   // LDS.128
            // simultaneous Horner: p, p', p''/2 share intermediates
            float h1 = fmaf(a.w, xr, a.z);
            float h2 = fmaf(h1,  xr, a.y);
            float h3 = fmaf(h2,  xr, a.x);
            float q2 = fmaf(a.w, xr, h1);
            float q3 = fmaf(q2,  xr, h2);
            float r  = fmaf(a.w, xr, q2);
            tv   += h3;
            dtv  += q3;
            ddtv += r;
        }
        dtv  *= 64.0f;    // p'/delta,      delta = 1/64 exactly
        ddtv *= 8192.0f;  // 2*r/delta^2

        // outer layer on t, domain [-3,3]
        float xs = 192.0f * (tv + 3.0f) / 6.0f;
        float fe = floor_div3(xs);
        fe = fminf(fmaxf(fe, 0.0f), 63.0f);
        float nl = 3.0f * fe;
        float xr = fmaf(2.0f * (xs - nl), THIRD, -1.0f);

        float4 b = sCout[(int)fe * KW + lane];             // LDS.128
        float y = fmaf(fmaf(fmaf(b.w, xr, b.z), xr, b.y), xr, b.x);

        if (i < I) {
            int o = i * KW + lane;
            out[o]          = y;
            out[o + IK]     = tv;
            out[o + 2 * IK] = dtv;
            out[o + 3 * IK] = ddtv;
        }
    }
}

extern "C" void kernel_launch(void* const* d_in, const int* in_sizes, int n_in,
                              void* d_out, int out_size)
{
    const float* x    = (const float*)d_in[0];
    const float* Win  = (const float*)d_in[1];
    const float* Wout = (const float*)d_in[2];
    float* out = (float*)d_out;

    int I = in_sizes[0] / NDIM;                 // 32768
    int grid = (I + TILE_I - 1) / TILE_I;       // 147

    kann_prep<<<(NC + 255) / 256, 256>>>(Win, Wout);

    cudaFuncSetAttribute(kann_kernel,
                         cudaFuncAttributeMaxDynamicSharedMemorySize, SMEM_BYTES);

    // PDL: main may launch while prep drains; it gates on g_coef via
    // cudaGridDependencySynchronize() after its x-only phase 1.
    cudaLaunchConfig_t cfg = {};
    cfg.gridDim  = dim3(grid, 1, 1);
    cfg.blockDim = dim3(THREADS, 1, 1);
    cfg.dynamicSmemBytes = SMEM_BYTES;
    cfg.stream = 0;
    cudaLaunchAttribute attrs[1];
    attrs[0].id = cudaLaunchAttributeProgrammaticStreamSerialization;
    attrs[0].val.programmaticStreamSerializationAllowed = 1;
    cfg.attrs = attrs;
    cfg.numAttrs = 1;
    cudaLaunchKernelEx(&cfg, kann_kernel, x, out, I);
}

// round 10
// speedup vs baseline: 1.1629x; 1.0201x over previous
#include <cuda_runtime.h>
#include <math.h>

namespace {
constexpr int NDIM   = 4;
constexpr int KW     = 32;      // N_WIDTH
constexpr int NN     = 193;     // N_NODES
constexpr int NELEM  = 64;
constexpr int TILE_I = 224;
constexpr int THREADS = 1024;
constexpr int IPW    = TILE_I / 32;            // samples per warp = 7

constexpr int KSL    = 8;                      // k per slice
constexpr int NSLICE = KW / KSL;               // 4
constexpr int RAW_IN_SL  = KSL * NN * NDIM;    // 6176 floats
constexpr int RAW_OUT_SL = KSL * NN;           // 1544 floats
constexpr int RAW_SL     = RAW_IN_SL + RAW_OUT_SL;  // 7720 floats

constexpr int NC_IN  = NELEM * 4 * KW;         // 8192 float4 (inner coeffs)
constexpr int NC_OUT = NELEM * KW;             // 2048 float4 (outer coeffs)

// smem layout in float4 units
constexpr int OFF_CIN  = 0;                    // [(e*4+j)*32 + k] -> a0..a3
constexpr int OFF_COUT = OFF_CIN  + NC_IN;     // [e*32 + k]      -> b0..b3
constexpr int OFF_XR   = OFF_COUT + NC_OUT;    // float4 [TILE_I]
constexpr int OFF_E4   = OFF_XR   + TILE_I;    // int4   [TILE_I]
constexpr int OFF_RAW  = OFF_E4   + TILE_I;    // raw slice, 7720 floats = 1930 f4
constexpr int SMEM_V4  = OFF_RAW  + (RAW_SL + 3) / 4;   // 12618
constexpr int SMEM_BYTES = SMEM_V4 * 16;       // 201888 B (1 CTA/SM)

constexpr float THIRD = 0.33333334f;           // RN(1/3)
}

// exact floor(div_rn(xs,3)) for xs in [0,192] without FP division
__device__ __forceinline__ float floor_div3(float xs) {
    float fe = floorf(xs * THIRD);
    float r  = fmaf(-3.0f, fe, xs);
    fe += (r >= 3.0f) ? 1.0f : 0.0f;
    fe -= (r < 0.0f)  ? 1.0f : 0.0f;
    return fe;
}

__global__ __launch_bounds__(THREADS, 1)
void kann_kernel(const float* __restrict__ x,
                 const float* __restrict__ Win,
                 const float* __restrict__ Wout,
                 float* __restrict__ out,
                 int I)
{
    extern __shared__ float4 smv[];
    float4* sCin  = smv + OFF_CIN;
    float4* sCout = smv + OFF_COUT;
    float4* sXR   = smv + OFF_XR;
    int4*   sE4   = (int4*)(smv + OFF_E4);
    float*  sXRf  = (float*)sXR;
    int*    sEf   = (int*)sE4;
    float*  sRaw  = (float*)(smv + OFF_RAW);         // Win slice [6176]
    float*  sRawO = sRaw + RAW_IN_SL;                // Wout slice [1544]

    const int tid    = threadIdx.x;
    const int i_base = blockIdx.x * TILE_I;

    // ---- phase 1: per-(sample,dim) transform (x-only) ----
    if (tid < TILE_I * NDIM) {
        const int li = tid >> 2;
        const int j  = tid & 3;
        const int i  = i_base + li;
        float xr = 0.f;
        int   ei = 0;
        if (i < I) {
            float v  = x[i * NDIM + j];
            float xs = 192.0f * (v + 1.0f) / 2.0f;   // exact /2
            float fe = floor_div3(xs);
            fe = fminf(fmaxf(fe, 0.0f), 63.0f);
            float nl = 3.0f * fe;                     // exact
            xr = fmaf(2.0f * (xs - nl), THIRD, -1.0f);
            ei = (int)fe;
        }
        sXRf[tid] = xr;
        sEf[tid]  = ei;
    }

    // ---- build coefficient tables in-kernel, 4 k-slices of 8 ----
    // basis -> monomial matrix, nodes {-1,-1/3,1/3,1}
    const float g00 = -0.0625f, g01 =  0.0625f, g02 =  0.5625f, g03 = -0.5625f;
    const float g10 =  0.5625f, g11 = -1.6875f, g12 = -0.5625f, g13 =  1.6875f;
    const float g20 =  0.5625f, g21 =  1.6875f, g22 = -0.5625f, g23 = -1.6875f;
    const float g30 = -0.0625f, g31 = -0.0625f, g32 =  0.5625f, g33 =  0.5625f;

    #pragma unroll
    for (int kq = 0; kq < NSLICE; kq++) {
        __syncthreads();                      // protect reused raw buffer
        // coalesced raw loads (weights are L2-resident after first wave)
        #pragma unroll
        for (int it = 0; it < RAW_IN_SL / THREADS + 1; it++) {
            int t = it * THREADS + tid;
            if (t < RAW_IN_SL) sRaw[t] = Win[kq * RAW_IN_SL + t];
        }
        if (tid < RAW_OUT_SL) sRawO[tid] = Wout[kq * RAW_OUT_SL + tid];
        else if (tid < RAW_OUT_SL + (THREADS - RAW_OUT_SL) &&
                 tid - (THREADS - RAW_OUT_SL) >= 0) { /* no-op filler */ }
        {
            int t = tid + THREADS;
            if (t - THREADS < RAW_OUT_SL - THREADS) {} // RAW_OUT_SL(1544) > 1024:
        }
        // second chunk of Wout slice
        {
            int t = THREADS + tid;
            if (t < RAW_OUT_SL) sRawO[t] = Wout[kq * RAW_OUT_SL + t];
        }
        __syncthreads();

        // inner coeffs: 2048 per slice, thread <-> (e,j,kk)
        #pragma unroll
        for (int it = 0; it < (NELEM * 4 * KSL) / THREADS; it++) {
            int idx = it * THREADS + tid;
            int kk  = idx & 7;
            int ej  = idx >> 3;               // e*4 + j
            int j   = ej & 3;
            int e   = ej >> 2;
            const float* w = sRaw + kk * (NN * NDIM) + (3 * e) * NDIM + j;
            float w0 = w[0], w1 = w[NDIM], w2 = w[2 * NDIM], w3 = w[3 * NDIM];
            float4 a;
            a.x = w0 * g00 + w1 * g10 + w2 * g20 + w3 * g30;
            a.y = w0 * g01 + w1 * g11 + w2 * g21 + w3 * g31;
            a.z = w0 * g02 + w1 * g12 + w2 * g22 + w3 * g32;
            a.w = w0 * g03 + w1 * g13 + w2 * g23 + w3 * g33;
            sCin[ej * KW + kq * KSL + kk] = a;
        }
        // outer coeffs: 512 per slice
        if (tid < NELEM * KSL) {
            int kk = tid & 7;
            int e  = tid >> 3;
            const float* w = sRawO + kk * NN + 3 * e;
            float w0 = w[0], w1 = w[1], w2 = w[2], w3 = w[3];
            float4 b;
            b.x = w0 * g00 + w1 * g10 + w2 * g20 + w3 * g30;
            b.y = w0 * g01 + w1 * g11 + w2 * g21 + w3 * g31;
            b.z = w0 * g02 + w1 * g12 + w2 * g22 + w3 * g32;
            b.w = w0 * g03 + w1 * g13 + w2 * g23 + w3 * g33;
            sCout[e * KW + kq * KSL + kk] = b;
        }
    }
    __syncthreads();

    // ---- phase 2: warp = one sample, lane = width k ----
    const int warp = tid >> 5;
    const int lane = tid & 31;
    const int IK   = I * KW;

    #pragma unroll
    for (int s = 0; s < IPW; s++) {
        const int li = warp * IPW + s;
        const int i  = i_base + li;
        const float4 xr4 = sXR[li];
        const int4   e4  = sE4[li];

        float tv = 0.f, dtv = 0.f, ddtv = 0.f;
        #pragma unroll
        for (int j = 0; j < 4; j++) {
            float xr = (j == 0) ? xr4.x : (j == 1) ? xr4.y : (j == 2) ? xr4.z : xr4.w;
            int   e  = (j == 0) ? e4.x  : (j == 1) ? e4.y  : (j == 2) ? e4.z  : e4.w;
            float4 a = sCin[((e << 2) | j) * KW + lane];   // LDS.128
            float h1 = fmaf(a.w, xr, a.z);
            float h2 = fmaf(h1,  xr, a.y);
            float h3 = fmaf(h2,  xr, a.x);
            float q2 = fmaf(a.w, xr, h1);
            float q3 = fmaf(q2,  xr, h2);
            float r  = fmaf(a.w, xr, q2);
            tv   += h3;
            dtv  += q3;
            ddtv += r;
        }
        dtv  *= 64.0f;    // p'/delta,      delta = 1/64 exactly
        ddtv *= 8192.0f;  // 2*r/delta^2

        // outer layer on t, domain [-3,3]
        float xs = 192.0f * (tv + 3.0f) / 6.0f;
        float fe = floor_div3(xs);
        fe = fminf(fmaxf(fe, 0.0f), 63.0f);
        float nl = 3.0f * fe;
        float xr = fmaf(2.0f * (xs - nl), THIRD, -1.0f);

        float4 b = sCout[(int)fe * KW + lane];             // LDS.128
        float y = fmaf(fmaf(fmaf(b.w, xr, b.z), xr, b.y), xr, b.x);

        if (i < I) {
            int o = i * KW + lane;
            out[o]          = y;
            out[o + IK]     = tv;
            out[o + 2 * IK] = dtv;
            out[o + 3 * IK] = ddtv;
        }
    }
}

extern "C" void kernel_launch(void* const* d_in, const int* in_sizes, int n_in,
                              void* d_out, int out_size)
{
    const float* x    = (const float*)d_in[0];
    const float* Win  = (const float*)d_in[1];
    const float* Wout = (const float*)d_in[2];
    float* out = (float*)d_out;

    int I = in_sizes[0] / NDIM;                 // 32768
    int grid = (I + TILE_I - 1) / TILE_I;       // 147

    cudaFuncSetAttribute(kann_kernel,
                         cudaFuncAttributeMaxDynamicSharedMemorySize, SMEM_BYTES);
    kann_kernel<<<grid, THREADS, SMEM_BYTES>>>(x, Win, Wout, out, I);
}